// round 1
// baseline (speedup 1.0000x reference)
#include <cuda_runtime.h>
#include <math.h>

#define NSEQ 256
#define DIM 64
#define NH 4
#define HDIM 16
#define NPOS (NSEQ * NSEQ)
#define NEGINF -1000000000.0f

// Scratch (allocation-free rule: __device__ globals)
__device__ float g_q[NPOS * DIM];
__device__ float g_k[NPOS * DIM];
__device__ float g_v[NPOS * DIM];
__device__ float g_gate[NPOS * DIM];
__device__ float g_go[NPOS * DIM];
__device__ float g_bm[NPOS * NH];   // layout [k][q][h]

// ---------------------------------------------------------------------------
// Kernel 1: LayerNorm + Q/K/V/Gate projections + fused (bias,mask) tensor.
// Block = 256 threads, 64 positions. Weights resident in dynamic SMEM.
// ---------------------------------------------------------------------------
__global__ __launch_bounds__(256) void proj_kernel(
    const float* __restrict__ x, const int* __restrict__ mask,
    const float* __restrict__ ln_s, const float* __restrict__ ln_b,
    const float* __restrict__ Wq, const float* __restrict__ Wk,
    const float* __restrict__ Wv, const float* __restrict__ Wg,
    const float* __restrict__ bg, const float* __restrict__ Wb)
{
    extern __shared__ float sm[];
    float* s_wq = sm;                 // 4096
    float* s_wk = s_wq + 4096;        // 4096
    float* s_wv = s_wk + 4096;        // 4096
    float* s_wg = s_wv + 4096;        // 4096
    float* s_wb = s_wg + 4096;        // 256
    float* s_xn = s_wb + 256;         // 64*65 (padded rows: conflict-free)
    float* s_bg = s_xn + 64 * 65;     // 64
    float* s_ls = s_bg + 64;          // 64
    float* s_lb = s_ls + 64;          // 64

    const int tid = threadIdx.x;
    for (int idx = tid; idx < 4096; idx += 256) {
        s_wq[idx] = Wq[idx];
        s_wk[idx] = Wk[idx];
        s_wv[idx] = Wv[idx];
        s_wg[idx] = Wg[idx];
    }
    if (tid < 256) s_wb[tid] = Wb[tid];
    if (tid < 64) { s_bg[tid] = bg[tid]; s_ls[tid] = ln_s[tid]; s_lb[tid] = ln_b[tid]; }
    __syncthreads();

    const int p0 = blockIdx.x * 64;

    // --- LayerNorm: one warp per position, 8 positions per warp ---
    const int lane = tid & 31;
    const int wrp = tid >> 5;
    for (int pp = wrp; pp < 64; pp += 8) {
        const float* xr = x + (p0 + pp) * DIM;
        float a = xr[lane];
        float b = xr[lane + 32];
        float sum = a + b;
        float sq = a * a + b * b;
        #pragma unroll
        for (int off = 16; off > 0; off >>= 1) {
            sum += __shfl_xor_sync(0xffffffffu, sum, off);
            sq  += __shfl_xor_sync(0xffffffffu, sq, off);
        }
        float mu  = sum * (1.0f / 64.0f);
        float var = sq * (1.0f / 64.0f) - mu * mu;
        float inv = rsqrtf(var + 1e-5f);
        s_xn[pp * 65 + lane]      = (a - mu) * inv * s_ls[lane]      + s_lb[lane];
        s_xn[pp * 65 + lane + 32] = (b - mu) * inv * s_ls[lane + 32] + s_lb[lane + 32];
    }
    __syncthreads();

    // --- Fused bias + mask -> g_bm[k][q][h]. thread = (position, head) ---
    {
        const int p = tid >> 2;   // 0..63
        const int h = tid & 3;
        float acc = 0.0f;
        #pragma unroll 8
        for (int d = 0; d < 64; ++d)
            acc = fmaf(s_xn[p * 65 + d], s_wb[d * 4 + h], acc);
        const int flat = p0 + p;
        const int r = flat >> 8;   // q index
        const int c = flat & 255;  // k index
        const float bm = (mask[flat] != 0) ? acc : NEGINF;  // ref replaces, not adds
        g_bm[(c * 256 + r) * 4 + h] = bm;
    }

    // --- Projections: thread = (column jj, position-group pz), 16 pos each ---
    const int jj = tid & 63;
    const int pz = tid >> 6;
    float aq[16], ak[16], av[16], ag[16];
    #pragma unroll
    for (int p = 0; p < 16; ++p) { aq[p] = 0.f; ak[p] = 0.f; av[p] = 0.f; ag[p] = 0.f; }

    #pragma unroll 4
    for (int d = 0; d < 64; ++d) {
        const float wq = s_wq[d * 64 + jj];
        const float wk = s_wk[d * 64 + jj];
        const float wv = s_wv[d * 64 + jj];
        const float wg = s_wg[d * 64 + jj];
        #pragma unroll
        for (int p = 0; p < 16; ++p) {
            const float xv = s_xn[(pz * 16 + p) * 65 + d];  // warp-broadcast
            aq[p] = fmaf(xv, wq, aq[p]);
            ak[p] = fmaf(xv, wk, ak[p]);
            av[p] = fmaf(xv, wv, av[p]);
            ag[p] = fmaf(xv, wg, ag[p]);
        }
    }
    #pragma unroll
    for (int p = 0; p < 16; ++p) {
        const int pos = p0 + pz * 16 + p;
        const int o = pos * 64 + jj;
        g_q[o] = aq[p];
        g_k[o] = ak[p];
        g_v[o] = av[p];
        const float gg = ag[p] + s_bg[jj];
        g_gate[o] = 1.0f / (1.0f + __expf(-gg));
    }
}

// ---------------------------------------------------------------------------
// Kernel 2: per-row attention. Block = (row i, q-half), 512 threads.
// thread = (q, h). K/V row in SMEM (128 KB). No running max (scores bounded;
// masked entries are exactly NEGINF + small dot -> exp underflows to 0).
// ---------------------------------------------------------------------------
__global__ __launch_bounds__(512) void attn_kernel()
{
    extern __shared__ float sm[];
    float* s_k = sm;                    // 16384 floats
    float* s_v = sm + NSEQ * DIM;       // 16384 floats
    const int i = blockIdx.x;
    const int tid = threadIdx.x;
    const int base = i * (NSEQ * DIM);

    {
        const float4* gk4 = (const float4*)(g_k + base);
        const float4* gv4 = (const float4*)(g_v + base);
        float4* sk4 = (float4*)s_k;
        float4* sv4 = (float4*)s_v;
        for (int idx = tid; idx < NSEQ * DIM / 4; idx += 512) {
            sk4[idx] = gk4[idx];
            sv4[idx] = gv4[idx];
        }
    }

    const int q = (tid >> 2) + (blockIdx.y << 7);
    const int h = tid & 3;

    float qr[16];
    {
        const float4* q4 = (const float4*)(g_q + base + q * 64 + h * 16);
        #pragma unroll
        for (int j = 0; j < 4; ++j) {
            float4 t = q4[j];
            qr[4 * j + 0] = t.x * 0.25f;   // 1/sqrt(HDIM) pre-folded into q
            qr[4 * j + 1] = t.y * 0.25f;
            qr[4 * j + 2] = t.z * 0.25f;
            qr[4 * j + 3] = t.w * 0.25f;
        }
    }
    __syncthreads();

    float l = 0.0f;
    float acc[16];
    #pragma unroll
    for (int d = 0; d < 16; ++d) acc[d] = 0.0f;

    const float* bmp = g_bm + q * 4 + h;   // bm[kk][q][h], warp-coalesced

    #pragma unroll 2
    for (int kk = 0; kk < NSEQ; ++kk) {
        const float4* kp = (const float4*)(s_k + kk * 64 + h * 16);
        float kb[16];
        #pragma unroll
        for (int j = 0; j < 4; ++j) *(float4*)&kb[4 * j] = kp[j];

        float d0 = qr[0] * kb[0];
        float d1 = qr[1] * kb[1];
        float d2 = qr[2] * kb[2];
        float d3 = qr[3] * kb[3];
        #pragma unroll
        for (int j = 4; j < 16; j += 4) {
            d0 = fmaf(qr[j + 0], kb[j + 0], d0);
            d1 = fmaf(qr[j + 1], kb[j + 1], d1);
            d2 = fmaf(qr[j + 2], kb[j + 2], d2);
            d3 = fmaf(qr[j + 3], kb[j + 3], d3);
        }
        const float s = (d0 + d1) + (d2 + d3) + bmp[kk * (NSEQ * NH)];
        const float p = __expf(s);
        l += p;

        const float4* vp = (const float4*)(s_v + kk * 64 + h * 16);
        float vb[16];
        #pragma unroll
        for (int j = 0; j < 4; ++j) *(float4*)&vb[4 * j] = vp[j];
        #pragma unroll
        for (int d = 0; d < 16; ++d) acc[d] = fmaf(p, vb[d], acc[d]);
    }

    const float inv = 1.0f / l;
    const float4* gg4 = (const float4*)(g_gate + base + q * 64 + h * 16);
    float4* go4 = (float4*)(g_go + base + q * 64 + h * 16);
    #pragma unroll
    for (int j = 0; j < 4; ++j) {
        float4 gt = gg4[j];
        float4 o;
        o.x = acc[4 * j + 0] * inv * gt.x;
        o.y = acc[4 * j + 1] * inv * gt.y;
        o.z = acc[4 * j + 2] * inv * gt.z;
        o.w = acc[4 * j + 3] * inv * gt.w;
        go4[j] = o;
    }
}

// ---------------------------------------------------------------------------
// Kernel 3: output projection  out = go @ Wo + bo
// ---------------------------------------------------------------------------
__global__ __launch_bounds__(256) void out_kernel(
    const float* __restrict__ Wo, const float* __restrict__ bo,
    float* __restrict__ out)
{
    __shared__ float s_wo[4096];
    __shared__ float s_go[64 * 65];
    __shared__ float s_bo[64];
    const int tid = threadIdx.x;
    const int p0 = blockIdx.x * 64;
    for (int idx = tid; idx < 4096; idx += 256) {
        s_wo[idx] = Wo[idx];
        const int p = idx >> 6;
        const int dd = idx & 63;
        s_go[p * 65 + dd] = g_go[(p0 + p) * 64 + dd];
    }
    if (tid < 64) s_bo[tid] = bo[tid];
    __syncthreads();

    const int jj = tid & 63;
    const int pz = tid >> 6;
    float acc[16];
    #pragma unroll
    for (int p = 0; p < 16; ++p) acc[p] = 0.0f;

    #pragma unroll 4
    for (int d = 0; d < 64; ++d) {
        const float w = s_wo[d * 64 + jj];
        #pragma unroll
        for (int p = 0; p < 16; ++p)
            acc[p] = fmaf(s_go[(pz * 16 + p) * 65 + d], w, acc[p]);
    }
    #pragma unroll
    for (int p = 0; p < 16; ++p)
        out[(p0 + pz * 16 + p) * 64 + jj] = acc[p] + s_bo[jj];
}

// ---------------------------------------------------------------------------
extern "C" void kernel_launch(void* const* d_in, const int* in_sizes, int n_in,
                              void* d_out, int out_size)
{
    const float* x    = (const float*)d_in[0];   // pair_repr (1,256,256,64)
    const int*   mask = (const int*)d_in[1];     // pair_mask (1,256,256)
    const float* ln_s = (const float*)d_in[2];
    const float* ln_b = (const float*)d_in[3];
    const float* Wq   = (const float*)d_in[4];
    const float* Wk   = (const float*)d_in[5];
    const float* Wv   = (const float*)d_in[6];
    const float* Wg   = (const float*)d_in[7];
    const float* bg   = (const float*)d_in[8];
    const float* Wb   = (const float*)d_in[9];
    const float* Wo   = (const float*)d_in[10];
    const float* bo   = (const float*)d_in[11];
    float* out = (float*)d_out;
    (void)in_sizes; (void)n_in; (void)out_size;

    const int sm1 = (4 * 4096 + 256 + 64 * 65 + 3 * 64) * (int)sizeof(float);  // 83968 B
    const int sm2 = 2 * NSEQ * DIM * (int)sizeof(float);                       // 131072 B
    cudaFuncSetAttribute(proj_kernel, cudaFuncAttributeMaxDynamicSharedMemorySize, sm1);
    cudaFuncSetAttribute(attn_kernel, cudaFuncAttributeMaxDynamicSharedMemorySize, sm2);

    proj_kernel<<<1024, 256, sm1>>>(x, mask, ln_s, ln_b, Wq, Wk, Wv, Wg, bg, Wb);
    dim3 agrid(256, 2, 1);
    attn_kernel<<<agrid, 512, sm2>>>();
    out_kernel<<<1024, 256>>>(Wo, bo, out);
}

// round 2
// speedup vs baseline: 1.0512x; 1.0512x over previous
#include <cuda_runtime.h>
#include <math.h>

#define NSEQ 256
#define DIM 64
#define NH 4
#define NPOS (NSEQ * NSEQ)
#define NEGINF -1000000000.0f

typedef unsigned long long u64;

// ---- packed fp32x2 helpers (Blackwell f32x2 pipe) ----
__device__ __forceinline__ u64 pack2(float lo, float hi) {
    u64 r; asm("mov.b64 %0, {%1, %2};" : "=l"(r) : "f"(lo), "f"(hi)); return r;
}
__device__ __forceinline__ u64 dup2(float v) { return pack2(v, v); }
__device__ __forceinline__ void unpack2(u64 v, float& lo, float& hi) {
    asm("mov.b64 {%0, %1}, %2;" : "=f"(lo), "=f"(hi) : "l"(v));
}
__device__ __forceinline__ void fma2(u64& d, u64 a, u64 b) {
    asm("fma.rn.f32x2 %0, %1, %2, %0;" : "+l"(d) : "l"(a), "l"(b));
}
__device__ __forceinline__ u64 mul2(u64 a, u64 b) {
    u64 r; asm("mul.rn.f32x2 %0, %1, %2;" : "=l"(r) : "l"(a), "l"(b)); return r;
}
__device__ __forceinline__ u64 add2(u64 a, u64 b) {
    u64 r; asm("add.rn.f32x2 %0, %1, %2;" : "=l"(r) : "l"(a), "l"(b)); return r;
}

// Scratch (__device__ globals: allocation-free rule)
__device__ float g_q[NPOS * DIM];
__device__ float g_k[NPOS * DIM];
__device__ float g_v[NPOS * DIM];
__device__ float g_gate[NPOS * DIM];
__device__ float g_bm[NPOS * NH];   // layout [k][q][h]

// ---------------------------------------------------------------------------
// Kernel 1 (persistent): LayerNorm + Q/K/V/Gate projections + fused bias/mask.
// grid = 296 blocks x 256 threads; weights staged in SMEM once per block.
// ---------------------------------------------------------------------------
__global__ __launch_bounds__(256, 2) void proj_kernel(
    const float* __restrict__ x, const int* __restrict__ mask,
    const float* __restrict__ ln_s, const float* __restrict__ ln_b,
    const float* __restrict__ Wq, const float* __restrict__ Wk,
    const float* __restrict__ Wv, const float* __restrict__ Wg,
    const float* __restrict__ bg, const float* __restrict__ Wb)
{
    extern __shared__ float sm[];
    float* s_wq = sm;                 // 4096
    float* s_wk = s_wq + 4096;        // 4096
    float* s_wv = s_wk + 4096;        // 4096
    float* s_wg = s_wv + 4096;        // 4096
    float* s_wb = s_wg + 4096;        // 256
    float* s_xt = s_wb + 256;         // transposed LN out: [d][pos], stride 66
    float* s_bg = s_xt + 64 * 66;     // 64
    float* s_ls = s_bg + 64;          // 64
    float* s_lb = s_ls + 64;          // 64

    const int tid = threadIdx.x;
    for (int idx = tid; idx < 4096; idx += 256) {
        s_wq[idx] = Wq[idx];
        s_wk[idx] = Wk[idx];
        s_wv[idx] = Wv[idx];
        s_wg[idx] = Wg[idx];
    }
    s_wb[tid] = Wb[tid];
    if (tid < 64) { s_bg[tid] = bg[tid]; s_ls[tid] = ln_s[tid]; s_lb[tid] = ln_b[tid]; }
    __syncthreads();

    const int lane = tid & 31;
    const int wrp  = tid >> 5;
    const int jj   = tid & 63;
    const int pz   = tid >> 6;    // 0..3 -> 16 positions each
    const int ph   = tid >> 2;    // 0..63 (bias position)
    const int hh   = tid & 3;     // head

    for (int c = blockIdx.x; c < 1024; c += gridDim.x) {
        const int p0 = c * 64;

        // --- LayerNorm: warp per position, store TRANSPOSED [d][pos] ---
        for (int pp = wrp; pp < 64; pp += 8) {
            const float* xr = x + (p0 + pp) * DIM;
            float a = xr[lane];
            float b = xr[lane + 32];
            float sum = a + b;
            float sq = a * a + b * b;
            #pragma unroll
            for (int off = 16; off > 0; off >>= 1) {
                sum += __shfl_xor_sync(0xffffffffu, sum, off);
                sq  += __shfl_xor_sync(0xffffffffu, sq, off);
            }
            float mu  = sum * (1.0f / 64.0f);
            float var = sq * (1.0f / 64.0f) - mu * mu;
            float inv = rsqrtf(var + 1e-5f);
            s_xt[lane * 66 + pp]        = (a - mu) * inv * s_ls[lane]      + s_lb[lane];
            s_xt[(lane + 32) * 66 + pp] = (b - mu) * inv * s_ls[lane + 32] + s_lb[lane + 32];
        }
        __syncthreads();

        // --- bias + mask -> g_bm[k][q][h] ---
        {
            float acc = 0.0f;
            #pragma unroll 8
            for (int d = 0; d < 64; ++d)
                acc = fmaf(s_xt[d * 66 + ph], s_wb[d * 4 + hh], acc);
            const int flat = p0 + ph;
            const int r = flat >> 8;    // q index
            const int cc = flat & 255;  // k index
            g_bm[(cc * 256 + r) * 4 + hh] = (mask[flat] != 0) ? acc : NEGINF;
        }

        // --- Projections: thread = (col jj, 16-position group pz), f32x2 pairs ---
        u64 aq[8], ak[8], av[8], ag[8];
        #pragma unroll
        for (int m = 0; m < 8; ++m) { aq[m] = 0ull; ak[m] = 0ull; av[m] = 0ull; ag[m] = 0ull; }

        #pragma unroll 2
        for (int d = 0; d < 64; ++d) {
            const u64 wq2 = dup2(s_wq[d * 64 + jj]);
            const u64 wk2 = dup2(s_wk[d * 64 + jj]);
            const u64 wv2 = dup2(s_wv[d * 64 + jj]);
            const u64 wg2 = dup2(s_wg[d * 64 + jj]);
            const u64* xp = (const u64*)(s_xt + d * 66 + pz * 16);  // broadcast LDS.64
            #pragma unroll
            for (int m = 0; m < 8; ++m) {
                const u64 xv = xp[m];
                fma2(aq[m], xv, wq2);
                fma2(ak[m], xv, wk2);
                fma2(av[m], xv, wv2);
                fma2(ag[m], xv, wg2);
            }
        }

        #pragma unroll
        for (int m = 0; m < 8; ++m) {
            const int o = (p0 + pz * 16 + 2 * m) * 64 + jj;
            float v0, v1;
            unpack2(aq[m], v0, v1); g_q[o] = v0; g_q[o + 64] = v1;
            unpack2(ak[m], v0, v1); g_k[o] = v0; g_k[o + 64] = v1;
            unpack2(av[m], v0, v1); g_v[o] = v0; g_v[o + 64] = v1;
            unpack2(ag[m], v0, v1);
            g_gate[o]      = 1.0f / (1.0f + __expf(-(v0 + s_bg[jj])));
            g_gate[o + 64] = 1.0f / (1.0f + __expf(-(v1 + s_bg[jj])));
        }
        __syncthreads();
    }
}

// ---------------------------------------------------------------------------
// Kernel 2: attention + gate + output projection, fused.
// Block = (row i, q-half), 512 threads = (q,h). K/V staged in 2 passes of
// 128 kk (64 KB smem -> 2 blocks/SM). Epilogue reuses smem for go^T / Wo.
// ---------------------------------------------------------------------------
__global__ __launch_bounds__(512, 2) void attn_kernel(
    const float* __restrict__ Wo, const float* __restrict__ bo,
    float* __restrict__ out)
{
    extern __shared__ float sm[];
    float* s_k = sm;            // 8192 floats (128 kk x 64 d)
    float* s_v = sm + 8192;     // 8192 floats
    // epilogue aliases (after sync):
    float* s_goT = sm;          // [64 d][130] = 8320 floats
    float* s_wo  = sm + 8320;   // 4096
    float* s_bo  = sm + 12416;  // 64

    const int i    = blockIdx.x;
    const int half = blockIdx.y;
    const int tid  = threadIdx.x;
    const int qloc = tid >> 2;           // 0..127
    const int q    = half * 128 + qloc;
    const int h    = tid & 3;
    const int base = i * (NSEQ * DIM);

    // q registers, pre-scaled by 1/sqrt(16)
    u64 qr[8];
    {
        const ulonglong2* q2 = (const ulonglong2*)(g_q + base + q * 64 + h * 16);
        const u64 sc = dup2(0.25f);
        #pragma unroll
        for (int j = 0; j < 4; ++j) {
            ulonglong2 t = q2[j];
            qr[2 * j]     = mul2(t.x, sc);
            qr[2 * j + 1] = mul2(t.y, sc);
        }
    }

    u64 acc[8];
    #pragma unroll
    for (int m = 0; m < 8; ++m) acc[m] = 0ull;
    float l = 0.0f;
    const float* gb = g_bm + q * 4 + h;

    #pragma unroll 1
    for (int pass = 0; pass < 2; ++pass) {
        __syncthreads();
        {
            const float4* gk4 = (const float4*)(g_k + base + pass * 8192);
            const float4* gv4 = (const float4*)(g_v + base + pass * 8192);
            float4* sk4 = (float4*)s_k;
            float4* sv4 = (float4*)s_v;
            #pragma unroll
            for (int t = 0; t < 4; ++t) {
                const int idx = tid + t * 512;
                sk4[idx] = gk4[idx];
                sv4[idx] = gv4[idx];
            }
        }
        __syncthreads();

        const float* gbp = gb + pass * 128 * (NSEQ * NH);
        #pragma unroll 1
        for (int kt = 0; kt < 128; kt += 8) {
            float bmv[8];
            #pragma unroll
            for (int j = 0; j < 8; ++j) bmv[j] = gbp[(kt + j) * (NSEQ * NH)];
            #pragma unroll
            for (int j = 0; j < 8; ++j) {
                const int kk = kt + j;
                const ulonglong2* kp = (const ulonglong2*)(s_k + kk * 64 + h * 16);
                ulonglong2 ka = kp[0], kb_ = kp[1], kc = kp[2], kd = kp[3];
                u64 t0 = mul2(qr[0], ka.x);
                u64 t1 = mul2(qr[1], ka.y);
                fma2(t0, qr[2], kb_.x);
                fma2(t1, qr[3], kb_.y);
                fma2(t0, qr[4], kc.x);
                fma2(t1, qr[5], kc.y);
                fma2(t0, qr[6], kd.x);
                fma2(t1, qr[7], kd.y);
                const u64 ts = add2(t0, t1);
                float lo, hi;
                unpack2(ts, lo, hi);
                const float p = __expf(lo + hi + bmv[j]);
                l += p;
                const u64 pd = dup2(p);
                const ulonglong2* vp = (const ulonglong2*)(s_v + kk * 64 + h * 16);
                ulonglong2 va = vp[0], vb_ = vp[1], vc = vp[2], vd = vp[3];
                fma2(acc[0], pd, va.x);
                fma2(acc[1], pd, va.y);
                fma2(acc[2], pd, vb_.x);
                fma2(acc[3], pd, vb_.y);
                fma2(acc[4], pd, vc.x);
                fma2(acc[5], pd, vc.y);
                fma2(acc[6], pd, vd.x);
                fma2(acc[7], pd, vd.y);
            }
        }
    }

    // gate * softmax-normalize
    u64 og[8];
    {
        const float inv = 1.0f / l;
        const u64 iv = dup2(inv);
        const ulonglong2* g2 = (const ulonglong2*)(g_gate + base + q * 64 + h * 16);
        #pragma unroll
        for (int j = 0; j < 4; ++j) {
            ulonglong2 t = g2[j];
            og[2 * j]     = mul2(mul2(acc[2 * j], iv), t.x);
            og[2 * j + 1] = mul2(mul2(acc[2 * j + 1], iv), t.y);
        }
    }

    __syncthreads();   // everyone done reading s_k/s_v

    // store go transposed: [d][qloc], stride 130
    #pragma unroll
    for (int j = 0; j < 8; ++j) {
        float lo, hi;
        unpack2(og[j], lo, hi);
        s_goT[(h * 16 + 2 * j) * 130 + qloc]     = lo;
        s_goT[(h * 16 + 2 * j + 1) * 130 + qloc] = hi;
    }
    for (int idx = tid; idx < 4096; idx += 512) s_wo[idx] = Wo[idx];
    if (tid < 64) s_bo[tid] = bo[tid];
    __syncthreads();

    // out = go @ Wo + bo : thread = (col jj, 16-q group pz)
    const int jj = tid & 63;
    const int pz = tid >> 6;    // 0..7
    u64 oa[8];
    #pragma unroll
    for (int m = 0; m < 8; ++m) oa[m] = 0ull;
    #pragma unroll 4
    for (int d = 0; d < 64; ++d) {
        const u64 w2 = dup2(s_wo[d * 64 + jj]);
        const u64* gp = (const u64*)(s_goT + d * 130 + pz * 16);  // broadcast LDS.64
        #pragma unroll
        for (int m = 0; m < 8; ++m) fma2(oa[m], gp[m], w2);
    }
    const float bov = s_bo[jj];
    #pragma unroll
    for (int m = 0; m < 8; ++m) {
        float lo, hi;
        unpack2(oa[m], lo, hi);
        const int qg = half * 128 + pz * 16 + 2 * m;
        out[(i * 256 + qg) * 64 + jj]     = lo + bov;
        out[(i * 256 + qg + 1) * 64 + jj] = hi + bov;
    }
}

// ---------------------------------------------------------------------------
extern "C" void kernel_launch(void* const* d_in, const int* in_sizes, int n_in,
                              void* d_out, int out_size)
{
    const float* x    = (const float*)d_in[0];
    const int*   mask = (const int*)d_in[1];
    const float* ln_s = (const float*)d_in[2];
    const float* ln_b = (const float*)d_in[3];
    const float* Wq   = (const float*)d_in[4];
    const float* Wk   = (const float*)d_in[5];
    const float* Wv   = (const float*)d_in[6];
    const float* Wg   = (const float*)d_in[7];
    const float* bg   = (const float*)d_in[8];
    const float* Wb   = (const float*)d_in[9];
    const float* Wo   = (const float*)d_in[10];
    const float* bo   = (const float*)d_in[11];
    float* out = (float*)d_out;
    (void)in_sizes; (void)n_in; (void)out_size;

    const int sm1 = (4 * 4096 + 256 + 64 * 66 + 3 * 64) * (int)sizeof(float);  // 84,736 B
    const int sm2 = 16384 * (int)sizeof(float);                                // 65,536 B
    cudaFuncSetAttribute(proj_kernel, cudaFuncAttributeMaxDynamicSharedMemorySize, sm1);
    cudaFuncSetAttribute(attn_kernel, cudaFuncAttributeMaxDynamicSharedMemorySize, sm2);

    proj_kernel<<<296, 256, sm1>>>(x, mask, ln_s, ln_b, Wq, Wk, Wv, Wg, bg, Wb);
    dim3 agrid(256, 2, 1);
    attn_kernel<<<agrid, 512, sm2>>>(Wo, bo, out);
}

// round 3
// speedup vs baseline: 2.2197x; 2.1115x over previous
#include <cuda_runtime.h>
#include <math.h>

#define NSEQ 256
#define DIM 64
#define NH 4
#define NPOS (NSEQ * NSEQ)
#define NEGINF -1000000000.0f

typedef unsigned long long u64;

// ---- packed fp32x2 helpers ----
__device__ __forceinline__ u64 pack2(float lo, float hi) {
    u64 r; asm("mov.b64 %0, {%1, %2};" : "=l"(r) : "f"(lo), "f"(hi)); return r;
}
__device__ __forceinline__ u64 dup2(float v) { return pack2(v, v); }
__device__ __forceinline__ void unpack2(u64 v, float& lo, float& hi) {
    asm("mov.b64 {%0, %1}, %2;" : "=f"(lo), "=f"(hi) : "l"(v));
}
__device__ __forceinline__ void fma2(u64& d, u64 a, u64 b) {
    asm("fma.rn.f32x2 %0, %1, %2, %0;" : "+l"(d) : "l"(a), "l"(b));
}
__device__ __forceinline__ u64 mul2(u64 a, u64 b) {
    u64 r; asm("mul.rn.f32x2 %0, %1, %2;" : "=l"(r) : "l"(a), "l"(b)); return r;
}
__device__ __forceinline__ u64 add2(u64 a, u64 b) {
    u64 r; asm("add.rn.f32x2 %0, %1, %2;" : "=l"(r) : "l"(a), "l"(b)); return r;
}

// Scratch
__device__ float g_q[NPOS * DIM];
__device__ float g_k[NPOS * DIM];
__device__ float g_v[NPOS * DIM];
__device__ float g_gate[NPOS * DIM];
__device__ float g_bm[NSEQ * NH * NSEQ];   // [k][h][q]

// ---------------------------------------------------------------------------
// Kernel 1 (persistent): LayerNorm + Q/K/V/Gate projections + fused bias/mask.
// ---------------------------------------------------------------------------
__global__ __launch_bounds__(256, 2) void proj_kernel(
    const float* __restrict__ x, const int* __restrict__ mask,
    const float* __restrict__ ln_s, const float* __restrict__ ln_b,
    const float* __restrict__ Wq, const float* __restrict__ Wk,
    const float* __restrict__ Wv, const float* __restrict__ Wg,
    const float* __restrict__ bg, const float* __restrict__ Wb)
{
    extern __shared__ float sm[];
    float* s_wq = sm;                 // 4096
    float* s_wk = s_wq + 4096;
    float* s_wv = s_wk + 4096;
    float* s_wg = s_wv + 4096;
    float* s_wb = s_wg + 4096;        // 256
    float* s_xt = s_wb + 256;         // [d][pos] stride 66
    float* s_bg = s_xt + 64 * 66;
    float* s_ls = s_bg + 64;
    float* s_lb = s_ls + 64;

    const int tid = threadIdx.x;
    for (int idx = tid; idx < 4096; idx += 256) {
        s_wq[idx] = Wq[idx];
        s_wk[idx] = Wk[idx];
        s_wv[idx] = Wv[idx];
        s_wg[idx] = Wg[idx];
    }
    s_wb[tid] = Wb[tid];
    if (tid < 64) { s_bg[tid] = bg[tid]; s_ls[tid] = ln_s[tid]; s_lb[tid] = ln_b[tid]; }
    __syncthreads();

    const int lane = tid & 31;
    const int wrp  = tid >> 5;
    const int jj   = tid & 63;
    const int pz   = tid >> 6;
    const int ph   = tid >> 2;
    const int hh   = tid & 3;

    for (int c = blockIdx.x; c < 1024; c += gridDim.x) {
        const int p0 = c * 64;

        for (int pp = wrp; pp < 64; pp += 8) {
            const float* xr = x + (p0 + pp) * DIM;
            float a = xr[lane];
            float b = xr[lane + 32];
            float sum = a + b;
            float sq = a * a + b * b;
            #pragma unroll
            for (int off = 16; off > 0; off >>= 1) {
                sum += __shfl_xor_sync(0xffffffffu, sum, off);
                sq  += __shfl_xor_sync(0xffffffffu, sq, off);
            }
            float mu  = sum * (1.0f / 64.0f);
            float var = sq * (1.0f / 64.0f) - mu * mu;
            float inv = rsqrtf(var + 1e-5f);
            s_xt[lane * 66 + pp]        = (a - mu) * inv * s_ls[lane]      + s_lb[lane];
            s_xt[(lane + 32) * 66 + pp] = (b - mu) * inv * s_ls[lane + 32] + s_lb[lane + 32];
        }
        __syncthreads();

        // bias + mask -> g_bm[k][h][q]
        {
            float acc = 0.0f;
            #pragma unroll 8
            for (int d = 0; d < 64; ++d)
                acc = fmaf(s_xt[d * 66 + ph], s_wb[d * 4 + hh], acc);
            const int flat = p0 + ph;
            const int r = flat >> 8;    // q
            const int cc = flat & 255;  // k
            g_bm[cc * (NH * NSEQ) + hh * NSEQ + r] = (mask[flat] != 0) ? acc : NEGINF;
        }

        u64 aq[8], ak[8], av[8], ag[8];
        #pragma unroll
        for (int m = 0; m < 8; ++m) { aq[m] = 0ull; ak[m] = 0ull; av[m] = 0ull; ag[m] = 0ull; }

        #pragma unroll 2
        for (int d = 0; d < 64; ++d) {
            const u64 wq2 = dup2(s_wq[d * 64 + jj]);
            const u64 wk2 = dup2(s_wk[d * 64 + jj]);
            const u64 wv2 = dup2(s_wv[d * 64 + jj]);
            const u64 wg2 = dup2(s_wg[d * 64 + jj]);
            const u64* xp = (const u64*)(s_xt + d * 66 + pz * 16);
            #pragma unroll
            for (int m = 0; m < 8; ++m) {
                const u64 xv = xp[m];
                fma2(aq[m], xv, wq2);
                fma2(ak[m], xv, wk2);
                fma2(av[m], xv, wv2);
                fma2(ag[m], xv, wg2);
            }
        }

        #pragma unroll
        for (int m = 0; m < 8; ++m) {
            const int o = (p0 + pz * 16 + 2 * m) * 64 + jj;
            float v0, v1;
            unpack2(aq[m], v0, v1); g_q[o] = v0; g_q[o + 64] = v1;
            unpack2(ak[m], v0, v1); g_k[o] = v0; g_k[o + 64] = v1;
            unpack2(av[m], v0, v1); g_v[o] = v0; g_v[o + 64] = v1;
            unpack2(ag[m], v0, v1);
            g_gate[o]      = 1.0f / (1.0f + __expf(-(v0 + s_bg[jj])));
            g_gate[o + 64] = 1.0f / (1.0f + __expf(-(v1 + s_bg[jj])));
        }
        __syncthreads();
    }
}

// ---------------------------------------------------------------------------
// Kernel 2: attention + gate + output projection, fused. Block = row i.
// 256 threads: thread = (q-group-of-4, head). K/V full row in SMEM,
// head-interleaved layout [kk][j][h][4] -> conflict-free broadcast LDS.128.
// ---------------------------------------------------------------------------
__global__ __launch_bounds__(256) void attn_kernel(
    const float* __restrict__ Wo, const float* __restrict__ bo,
    float* __restrict__ out)
{
    extern __shared__ float sm[];
    float* s_k = sm;             // 16384 f, permuted [kk][j][h][4]
    float* s_v = sm + 16384;     // 16384 f
    // epilogue aliases (after attention, K/V dead):
    float* s_goT = sm;           // [64 d][260] = 16640 f
    float* s_wo  = sm + 16640;   // 4096
    float* s_bo  = sm + 20736;   // 64

    const int i   = blockIdx.x;
    const int tid = threadIdx.x;
    const int qg  = tid >> 2;    // 0..63
    const int h   = tid & 3;
    const int q0  = qg * 4;
    const int base = i * (NSEQ * DIM);

    // Stage K/V with head-interleave permute: src d = h*16 + j*4 + e
    // dst offset = kk*64 + j*16 + h*4 + e
    {
        const float4* gk4 = (const float4*)(g_k + base);
        const float4* gv4 = (const float4*)(g_v + base);
        #pragma unroll
        for (int it = 0; it < 16; ++it) {
            const int idx = it * 256 + tid;      // f4 index
            const int kk = idx >> 4;
            const int d4 = idx & 15;             // h = d4>>2, j = d4&3
            const int dst = kk * 64 + (d4 & 3) * 16 + (d4 >> 2) * 4;
            *(float4*)(s_k + dst) = gk4[idx];
            *(float4*)(s_v + dst) = gv4[idx];
        }
    }

    // q registers for 4 q's, pre-scaled by 1/sqrt(16)
    u64 qr[4][8];
    {
        const u64 sc = dup2(0.25f);
        #pragma unroll
        for (int qq = 0; qq < 4; ++qq) {
            const ulonglong2* q2 = (const ulonglong2*)(g_q + base + (q0 + qq) * 64 + h * 16);
            #pragma unroll
            for (int j = 0; j < 4; ++j) {
                ulonglong2 t = q2[j];
                qr[qq][2 * j]     = mul2(t.x, sc);
                qr[qq][2 * j + 1] = mul2(t.y, sc);
            }
        }
    }
    __syncthreads();

    u64 acc[4][8];
    #pragma unroll
    for (int qq = 0; qq < 4; ++qq)
        #pragma unroll
        for (int m = 0; m < 8; ++m) acc[qq][m] = 0ull;
    float l[4] = {0.f, 0.f, 0.f, 0.f};

    const float* bmb = g_bm + h * NSEQ + q0;   // + kk*1024
    float4 bm_cur = *(const float4*)bmb;

    #pragma unroll 1
    for (int kk = 0; kk < 256; ++kk) {
        float4 bm_next;
        if (kk < 255) bm_next = __ldg((const float4*)(bmb + (kk + 1) * (NH * NSEQ)));

        const ulonglong2* kp = (const ulonglong2*)(s_k + kk * 64 + h * 4);
        // j-th 16B chunk at stride 16 floats = 8 u64: kp index j*2? 16 floats = 4*? 
        // s_k row: [j][h][4]: chunk j at offset j*16 floats; thread reads h*4..h*4+3
        // BUT we need 16 contiguous floats per thread? No: thread's d-slice is
        // spread: (j,h) -> 4 floats each j. Load 4x float4 (16B) at j*16+h*4.
        u64 kb[8];
        {
            const u64* kpu = (const u64*)(s_k + kk * 64);
            #pragma unroll
            for (int j = 0; j < 4; ++j) {
                kb[2 * j]     = kpu[j * 8 + h * 2];
                kb[2 * j + 1] = kpu[j * 8 + h * 2 + 1];
            }
        }

        float p[4];
        #pragma unroll
        for (int qq = 0; qq < 4; ++qq) {
            u64 t0 = mul2(qr[qq][0], kb[0]);
            u64 t1 = mul2(qr[qq][1], kb[1]);
            fma2(t0, qr[qq][2], kb[2]);
            fma2(t1, qr[qq][3], kb[3]);
            fma2(t0, qr[qq][4], kb[4]);
            fma2(t1, qr[qq][5], kb[5]);
            fma2(t0, qr[qq][6], kb[6]);
            fma2(t1, qr[qq][7], kb[7]);
            const u64 ts = add2(t0, t1);
            float lo, hi;
            unpack2(ts, lo, hi);
            const float bmq = (qq == 0) ? bm_cur.x : (qq == 1) ? bm_cur.y
                              : (qq == 2) ? bm_cur.z : bm_cur.w;
            p[qq] = __expf(lo + hi + bmq);
            l[qq] += p[qq];
        }

        u64 vb[8];
        {
            const u64* vpu = (const u64*)(s_v + kk * 64);
            #pragma unroll
            for (int j = 0; j < 4; ++j) {
                vb[2 * j]     = vpu[j * 8 + h * 2];
                vb[2 * j + 1] = vpu[j * 8 + h * 2 + 1];
            }
        }
        #pragma unroll
        for (int qq = 0; qq < 4; ++qq) {
            const u64 pd = dup2(p[qq]);
            #pragma unroll
            for (int m = 0; m < 8; ++m) fma2(acc[qq][m], pd, vb[m]);
        }
        bm_cur = bm_next;
    }

    __syncthreads();   // K/V reads done; smem re-used

    // gate * normalize -> s_goT[d][q] (stride 260)
    #pragma unroll
    for (int qq = 0; qq < 4; ++qq) {
        const float inv = 1.0f / l[qq];
        const u64 iv = dup2(inv);
        const ulonglong2* g2 = (const ulonglong2*)(g_gate + base + (q0 + qq) * 64 + h * 16);
        #pragma unroll
        for (int j = 0; j < 4; ++j) {
            ulonglong2 t = g2[j];
            u64 o0 = mul2(mul2(acc[qq][2 * j], iv), t.x);
            u64 o1 = mul2(mul2(acc[qq][2 * j + 1], iv), t.y);
            float a0, a1, b0, b1;
            unpack2(o0, a0, a1);
            unpack2(o1, b0, b1);
            const int db = h * 16 + j * 4;
            s_goT[(db + 0) * 260 + q0 + qq] = a0;
            s_goT[(db + 1) * 260 + q0 + qq] = a1;
            s_goT[(db + 2) * 260 + q0 + qq] = b0;
            s_goT[(db + 3) * 260 + q0 + qq] = b1;
        }
    }
    for (int idx = tid; idx < 4096; idx += 256) s_wo[idx] = Wo[idx];
    if (tid < 64) s_bo[tid] = bo[tid];
    __syncthreads();

    // out = go @ Wo + bo : thread = (col jj, 64-q group pz)
    const int jj = tid & 63;
    const int pz = tid >> 6;    // 0..3
    u64 oa[32];
    #pragma unroll
    for (int m = 0; m < 32; ++m) oa[m] = 0ull;
    #pragma unroll 2
    for (int d = 0; d < 64; ++d) {
        const u64 w2 = dup2(s_wo[d * 64 + jj]);
        const u64* gp = (const u64*)(s_goT + d * 260 + pz * 64);
        #pragma unroll
        for (int m = 0; m < 32; ++m) fma2(oa[m], gp[m], w2);
    }
    const float bov = s_bo[jj];
    float* op = out + (i * 256 + pz * 64) * 64 + jj;
    #pragma unroll
    for (int m = 0; m < 32; ++m) {
        float lo, hi;
        unpack2(oa[m], lo, hi);
        op[(2 * m) * 64]     = lo + bov;
        op[(2 * m + 1) * 64] = hi + bov;
    }
}

// ---------------------------------------------------------------------------
extern "C" void kernel_launch(void* const* d_in, const int* in_sizes, int n_in,
                              void* d_out, int out_size)
{
    const float* x    = (const float*)d_in[0];
    const int*   mask = (const int*)d_in[1];
    const float* ln_s = (const float*)d_in[2];
    const float* ln_b = (const float*)d_in[3];
    const float* Wq   = (const float*)d_in[4];
    const float* Wk   = (const float*)d_in[5];
    const float* Wv   = (const float*)d_in[6];
    const float* Wg   = (const float*)d_in[7];
    const float* bg   = (const float*)d_in[8];
    const float* Wb   = (const float*)d_in[9];
    const float* Wo   = (const float*)d_in[10];
    const float* bo   = (const float*)d_in[11];
    float* out = (float*)d_out;
    (void)in_sizes; (void)n_in; (void)out_size;

    const int sm1 = (4 * 4096 + 256 + 64 * 66 + 3 * 64) * (int)sizeof(float);
    const int sm2 = 2 * NSEQ * DIM * (int)sizeof(float);   // 131072 B
    cudaFuncSetAttribute(proj_kernel, cudaFuncAttributeMaxDynamicSharedMemorySize, sm1);
    cudaFuncSetAttribute(attn_kernel, cudaFuncAttributeMaxDynamicSharedMemorySize, sm2);

    proj_kernel<<<296, 256, sm1>>>(x, mask, ln_s, ln_b, Wq, Wk, Wv, Wg, bg, Wb);
    attn_kernel<<<256, 256, sm2>>>(Wo, bo, out);
}

// round 4
// speedup vs baseline: 2.4167x; 1.0888x over previous
#include <cuda_runtime.h>
#include <math.h>

#define NSEQ 256
#define DIM 64
#define NH 4
#define NPOS (NSEQ * NSEQ)
#define NEGINF -1000000000.0f

typedef unsigned long long u64;

// ---- packed fp32x2 helpers ----
__device__ __forceinline__ u64 pack2(float lo, float hi) {
    u64 r; asm("mov.b64 %0, {%1, %2};" : "=l"(r) : "f"(lo), "f"(hi)); return r;
}
__device__ __forceinline__ u64 dup2(float v) { return pack2(v, v); }
__device__ __forceinline__ void unpack2(u64 v, float& lo, float& hi) {
    asm("mov.b64 {%0, %1}, %2;" : "=f"(lo), "=f"(hi) : "l"(v));
}
__device__ __forceinline__ void fma2(u64& d, u64 a, u64 b) {
    asm("fma.rn.f32x2 %0, %1, %2, %0;" : "+l"(d) : "l"(a), "l"(b));
}
__device__ __forceinline__ u64 mul2(u64 a, u64 b) {
    u64 r; asm("mul.rn.f32x2 %0, %1, %2;" : "=l"(r) : "l"(a), "l"(b)); return r;
}
__device__ __forceinline__ u64 add2(u64 a, u64 b) {
    u64 r; asm("add.rn.f32x2 %0, %1, %2;" : "=l"(r) : "l"(a), "l"(b)); return r;
}

// Scratch
__device__ float g_q[NPOS * DIM];
__device__ float g_k[NPOS * DIM];
__device__ float g_v[NPOS * DIM];
__device__ float g_gate[NPOS * DIM];
__device__ float g_bm[NSEQ * NH * NSEQ];   // [k][h][q]

// ---------------------------------------------------------------------------
// Kernel 1 (persistent): LayerNorm + Q/K/V/Gate projections + fused bias/mask.
// ---------------------------------------------------------------------------
__global__ __launch_bounds__(256, 2) void proj_kernel(
    const float* __restrict__ x, const int* __restrict__ mask,
    const float* __restrict__ ln_s, const float* __restrict__ ln_b,
    const float* __restrict__ Wq, const float* __restrict__ Wk,
    const float* __restrict__ Wv, const float* __restrict__ Wg,
    const float* __restrict__ bg, const float* __restrict__ Wb)
{
    extern __shared__ float sm[];
    float* s_wq = sm;                 // 4096
    float* s_wk = s_wq + 4096;
    float* s_wv = s_wk + 4096;
    float* s_wg = s_wv + 4096;
    float* s_wb = s_wg + 4096;        // 256
    float* s_xt = s_wb + 256;         // [d][pos] stride 66
    float* s_bg = s_xt + 64 * 66;
    float* s_ls = s_bg + 64;
    float* s_lb = s_ls + 64;

    const int tid = threadIdx.x;
    for (int idx = tid; idx < 4096; idx += 256) {
        s_wq[idx] = Wq[idx];
        s_wk[idx] = Wk[idx];
        s_wv[idx] = Wv[idx];
        s_wg[idx] = Wg[idx];
    }
    s_wb[tid] = Wb[tid];
    if (tid < 64) { s_bg[tid] = bg[tid]; s_ls[tid] = ln_s[tid]; s_lb[tid] = ln_b[tid]; }
    __syncthreads();

    const int lane = tid & 31;
    const int wrp  = tid >> 5;
    const int jj   = tid & 63;
    const int pz   = tid >> 6;
    const int ph   = tid >> 2;
    const int hh   = tid & 3;

    for (int c = blockIdx.x; c < 1024; c += gridDim.x) {
        const int p0 = c * 64;

        for (int pp = wrp; pp < 64; pp += 8) {
            const float* xr = x + (p0 + pp) * DIM;
            float a = xr[lane];
            float b = xr[lane + 32];
            float sum = a + b;
            float sq = a * a + b * b;
            #pragma unroll
            for (int off = 16; off > 0; off >>= 1) {
                sum += __shfl_xor_sync(0xffffffffu, sum, off);
                sq  += __shfl_xor_sync(0xffffffffu, sq, off);
            }
            float mu  = sum * (1.0f / 64.0f);
            float var = sq * (1.0f / 64.0f) - mu * mu;
            float inv = rsqrtf(var + 1e-5f);
            s_xt[lane * 66 + pp]        = (a - mu) * inv * s_ls[lane]      + s_lb[lane];
            s_xt[(lane + 32) * 66 + pp] = (b - mu) * inv * s_ls[lane + 32] + s_lb[lane + 32];
        }
        __syncthreads();

        // bias + mask -> g_bm[k][h][q]
        {
            float acc = 0.0f;
            #pragma unroll 8
            for (int d = 0; d < 64; ++d)
                acc = fmaf(s_xt[d * 66 + ph], s_wb[d * 4 + hh], acc);
            const int flat = p0 + ph;
            const int r = flat >> 8;    // q
            const int cc = flat & 255;  // k
            g_bm[cc * (NH * NSEQ) + hh * NSEQ + r] = (mask[flat] != 0) ? acc : NEGINF;
        }

        u64 aq[8], ak[8], av[8], ag[8];
        #pragma unroll
        for (int m = 0; m < 8; ++m) { aq[m] = 0ull; ak[m] = 0ull; av[m] = 0ull; ag[m] = 0ull; }

        #pragma unroll 2
        for (int d = 0; d < 64; ++d) {
            const u64 wq2 = dup2(s_wq[d * 64 + jj]);
            const u64 wk2 = dup2(s_wk[d * 64 + jj]);
            const u64 wv2 = dup2(s_wv[d * 64 + jj]);
            const u64 wg2 = dup2(s_wg[d * 64 + jj]);
            const u64* xp = (const u64*)(s_xt + d * 66 + pz * 16);
            #pragma unroll
            for (int m = 0; m < 8; ++m) {
                const u64 xv = xp[m];
                fma2(aq[m], xv, wq2);
                fma2(ak[m], xv, wk2);
                fma2(av[m], xv, wv2);
                fma2(ag[m], xv, wg2);
            }
        }

        #pragma unroll
        for (int m = 0; m < 8; ++m) {
            const int o = (p0 + pz * 16 + 2 * m) * 64 + jj;
            float v0, v1;
            unpack2(aq[m], v0, v1); g_q[o] = v0; g_q[o + 64] = v1;
            unpack2(ak[m], v0, v1); g_k[o] = v0; g_k[o + 64] = v1;
            unpack2(av[m], v0, v1); g_v[o] = v0; g_v[o + 64] = v1;
            unpack2(ag[m], v0, v1);
            g_gate[o]      = 1.0f / (1.0f + __expf(-(v0 + s_bg[jj])));
            g_gate[o + 64] = 1.0f / (1.0f + __expf(-(v1 + s_bg[jj])));
        }
        __syncthreads();
    }
}

// ---------------------------------------------------------------------------
// Kernel 2: attention + gate + output projection, fused. Block = row i.
// 512 threads: thread = (q-group-of-2, head) -> 16 warps/SM (4/SMSP).
// K/V full row in SMEM, head-interleaved [kk][j][h][4]; K/V reads are
// LDS.128 broadcast wavefronts (4 addr x 16B = 64B).
// ---------------------------------------------------------------------------
__global__ __launch_bounds__(512, 1) void attn_kernel(
    const float* __restrict__ Wo, const float* __restrict__ bo,
    float* __restrict__ out)
{
    extern __shared__ float sm[];
    float* s_k = sm;             // 16384 f, permuted [kk][j][h][4]
    float* s_v = sm + 16384;     // 16384 f
    // epilogue aliases (after attention, K/V dead):
    float* s_goT = sm;           // [64 d][260] = 16640 f
    float* s_wo  = sm + 16640;   // 4096
    float* s_bo  = sm + 20736;   // 64

    const int i   = blockIdx.x;
    const int tid = threadIdx.x;
    const int qg  = tid >> 2;    // 0..127
    const int h   = tid & 3;
    const int q0  = qg * 2;
    const int base = i * (NSEQ * DIM);

    // Stage K/V with head-interleave permute: src d = h*16 + j*4 + e
    // dst offset = kk*64 + j*16 + h*4 + e
    {
        const float4* gk4 = (const float4*)(g_k + base);
        const float4* gv4 = (const float4*)(g_v + base);
        #pragma unroll
        for (int it = 0; it < 8; ++it) {
            const int idx = it * 512 + tid;      // f4 index, 4096 total
            const int kk = idx >> 4;
            const int d4 = idx & 15;
            const int dst = kk * 64 + (d4 & 3) * 16 + (d4 >> 2) * 4;
            *(float4*)(s_k + dst) = gk4[idx];
            *(float4*)(s_v + dst) = gv4[idx];
        }
    }

    // q registers for 2 q's, pre-scaled by 1/sqrt(16)
    u64 qr[2][8];
    {
        const u64 sc = dup2(0.25f);
        #pragma unroll
        for (int qq = 0; qq < 2; ++qq) {
            const ulonglong2* q2 = (const ulonglong2*)(g_q + base + (q0 + qq) * 64 + h * 16);
            #pragma unroll
            for (int j = 0; j < 4; ++j) {
                ulonglong2 t = q2[j];
                qr[qq][2 * j]     = mul2(t.x, sc);
                qr[qq][2 * j + 1] = mul2(t.y, sc);
            }
        }
    }
    __syncthreads();

    u64 acc[2][8];
    #pragma unroll
    for (int qq = 0; qq < 2; ++qq)
        #pragma unroll
        for (int m = 0; m < 8; ++m) acc[qq][m] = 0ull;
    float l[2] = {0.f, 0.f};

    const float* bmb = g_bm + h * NSEQ + q0;   // + kk*1024
    float2 bm_cur = *(const float2*)bmb;

    #pragma unroll 2
    for (int kk = 0; kk < 256; ++kk) {
        float2 bm_next;
        if (kk < 255) bm_next = __ldg((const float2*)(bmb + (kk + 1) * (NH * NSEQ)));

        // K slice: 4 x LDS.128 (ull2 index j*4 + h)
        u64 kb[8];
        {
            const ulonglong2* kpu = (const ulonglong2*)(s_k + kk * 64);
            #pragma unroll
            for (int j = 0; j < 4; ++j) {
                ulonglong2 t = kpu[j * 4 + h];
                kb[2 * j]     = t.x;
                kb[2 * j + 1] = t.y;
            }
        }

        float p[2];
        #pragma unroll
        for (int qq = 0; qq < 2; ++qq) {
            u64 t0 = mul2(qr[qq][0], kb[0]);
            u64 t1 = mul2(qr[qq][1], kb[1]);
            fma2(t0, qr[qq][2], kb[2]);
            fma2(t1, qr[qq][3], kb[3]);
            fma2(t0, qr[qq][4], kb[4]);
            fma2(t1, qr[qq][5], kb[5]);
            fma2(t0, qr[qq][6], kb[6]);
            fma2(t1, qr[qq][7], kb[7]);
            const u64 ts = add2(t0, t1);
            float lo, hi;
            unpack2(ts, lo, hi);
            const float bmq = (qq == 0) ? bm_cur.x : bm_cur.y;
            p[qq] = __expf(lo + hi + bmq);
            l[qq] += p[qq];
        }

        u64 vb[8];
        {
            const ulonglong2* vpu = (const ulonglong2*)(s_v + kk * 64);
            #pragma unroll
            for (int j = 0; j < 4; ++j) {
                ulonglong2 t = vpu[j * 4 + h];
                vb[2 * j]     = t.x;
                vb[2 * j + 1] = t.y;
            }
        }
        const u64 p0d = dup2(p[0]);
        const u64 p1d = dup2(p[1]);
        #pragma unroll
        for (int m = 0; m < 8; ++m) fma2(acc[0][m], p0d, vb[m]);
        #pragma unroll
        for (int m = 0; m < 8; ++m) fma2(acc[1][m], p1d, vb[m]);
        bm_cur = bm_next;
    }

    __syncthreads();   // K/V reads done; smem re-used

    // gate * normalize -> s_goT[d][q] (stride 260)
    #pragma unroll
    for (int qq = 0; qq < 2; ++qq) {
        const float inv = 1.0f / l[qq];
        const u64 iv = dup2(inv);
        const ulonglong2* g2 = (const ulonglong2*)(g_gate + base + (q0 + qq) * 64 + h * 16);
        #pragma unroll
        for (int j = 0; j < 4; ++j) {
            ulonglong2 t = g2[j];
            u64 o0 = mul2(mul2(acc[qq][2 * j], iv), t.x);
            u64 o1 = mul2(mul2(acc[qq][2 * j + 1], iv), t.y);
            float a0, a1, b0, b1;
            unpack2(o0, a0, a1);
            unpack2(o1, b0, b1);
            const int db = h * 16 + j * 4;
            s_goT[(db + 0) * 260 + q0 + qq] = a0;
            s_goT[(db + 1) * 260 + q0 + qq] = a1;
            s_goT[(db + 2) * 260 + q0 + qq] = b0;
            s_goT[(db + 3) * 260 + q0 + qq] = b1;
        }
    }
    for (int idx = tid; idx < 4096; idx += 512) s_wo[idx] = Wo[idx];
    if (tid < 64) s_bo[tid] = bo[tid];
    __syncthreads();

    // out = go @ Wo + bo : thread = (col jj, 32-q group pz)
    const int jj = tid & 63;
    const int pz = tid >> 6;    // 0..7
    u64 oa[16];
    #pragma unroll
    for (int m = 0; m < 16; ++m) oa[m] = 0ull;
    #pragma unroll 4
    for (int d = 0; d < 64; ++d) {
        const u64 w2 = dup2(s_wo[d * 64 + jj]);
        const u64* gp = (const u64*)(s_goT + d * 260 + pz * 32);
        #pragma unroll
        for (int m = 0; m < 16; ++m) fma2(oa[m], gp[m], w2);
    }
    const float bov = s_bo[jj];
    float* op = out + (i * 256 + pz * 32) * 64 + jj;
    #pragma unroll
    for (int m = 0; m < 16; ++m) {
        float lo, hi;
        unpack2(oa[m], lo, hi);
        op[(2 * m) * 64]     = lo + bov;
        op[(2 * m + 1) * 64] = hi + bov;
    }
}

// ---------------------------------------------------------------------------
extern "C" void kernel_launch(void* const* d_in, const int* in_sizes, int n_in,
                              void* d_out, int out_size)
{
    const float* x    = (const float*)d_in[0];
    const int*   mask = (const int*)d_in[1];
    const float* ln_s = (const float*)d_in[2];
    const float* ln_b = (const float*)d_in[3];
    const float* Wq   = (const float*)d_in[4];
    const float* Wk   = (const float*)d_in[5];
    const float* Wv   = (const float*)d_in[6];
    const float* Wg   = (const float*)d_in[7];
    const float* bg   = (const float*)d_in[8];
    const float* Wb   = (const float*)d_in[9];
    const float* Wo   = (const float*)d_in[10];
    const float* bo   = (const float*)d_in[11];
    float* out = (float*)d_out;
    (void)in_sizes; (void)n_in; (void)out_size;

    const int sm1 = (4 * 4096 + 256 + 64 * 66 + 3 * 64) * (int)sizeof(float);
    const int sm2 = 2 * NSEQ * DIM * (int)sizeof(float);   // 131072 B
    cudaFuncSetAttribute(proj_kernel, cudaFuncAttributeMaxDynamicSharedMemorySize, sm1);
    cudaFuncSetAttribute(attn_kernel, cudaFuncAttributeMaxDynamicSharedMemorySize, sm2);

    proj_kernel<<<296, 256, sm1>>>(x, mask, ln_s, ln_b, Wq, Wk, Wv, Wg, bg, Wb);
    attn_kernel<<<256, 512, sm2>>>(Wo, bo, out);
}

// round 6
// speedup vs baseline: 2.7070x; 1.1201x over previous
#include <cuda_runtime.h>
#include <cuda_bf16.h>
#include <math.h>

#define NSEQ 256
#define DIM 64
#define NH 4
#define NPOS (NSEQ * NSEQ)
#define NEGINF -1000000000.0f

typedef unsigned long long u64;

// ---- packed fp32x2 helpers ----
__device__ __forceinline__ u64 pack2(float lo, float hi) {
    u64 r; asm("mov.b64 %0, {%1, %2};" : "=l"(r) : "f"(lo), "f"(hi)); return r;
}
__device__ __forceinline__ u64 dup2(float v) { return pack2(v, v); }
__device__ __forceinline__ void unpack2(u64 v, float& lo, float& hi) {
    asm("mov.b64 {%0, %1}, %2;" : "=f"(lo), "=f"(hi) : "l"(v));
}
__device__ __forceinline__ void fma2(u64& d, u64 a, u64 b) {
    asm("fma.rn.f32x2 %0, %1, %2, %0;" : "+l"(d) : "l"(a), "l"(b));
}
__device__ __forceinline__ u64 mul2(u64 a, u64 b) {
    u64 r; asm("mul.rn.f32x2 %0, %1, %2;" : "=l"(r) : "l"(a), "l"(b)); return r;
}
__device__ __forceinline__ u64 add2(u64 a, u64 b) {
    u64 r; asm("add.rn.f32x2 %0, %1, %2;" : "=l"(r) : "l"(a), "l"(b)); return r;
}
// bf16 pair (u32) -> packed fp32 pair (u64). 2 PRMT on the ALU pipe.
__device__ __forceinline__ u64 bf2f2(unsigned int u) {
    return pack2(__uint_as_float(__byte_perm(u, 0, 0x1044)),
                 __uint_as_float(__byte_perm(u, 0, 0x3244)));
}

// Scratch
__device__ float g_q[NPOS * DIM];
__device__ float g_k[NPOS * DIM];
__device__ float g_v[NPOS * DIM];
__device__ float g_gate[NPOS * DIM];
__device__ float g_bm[NSEQ * NH * NSEQ];   // [k][h][q]

// ---------------------------------------------------------------------------
// Kernel 1 (persistent): LayerNorm + Q/K/V/Gate projections + fused bias/mask.
// ---------------------------------------------------------------------------
__global__ __launch_bounds__(256, 2) void proj_kernel(
    const float* __restrict__ x, const int* __restrict__ mask,
    const float* __restrict__ ln_s, const float* __restrict__ ln_b,
    const float* __restrict__ Wq, const float* __restrict__ Wk,
    const float* __restrict__ Wv, const float* __restrict__ Wg,
    const float* __restrict__ bg, const float* __restrict__ Wb)
{
    extern __shared__ float sm[];
    float* s_wq = sm;                 // 4096
    float* s_wk = s_wq + 4096;
    float* s_wv = s_wk + 4096;
    float* s_wg = s_wv + 4096;
    float* s_wb = s_wg + 4096;        // 256
    float* s_xt = s_wb + 256;         // [d][pos] stride 66
    float* s_bg = s_xt + 64 * 66;
    float* s_ls = s_bg + 64;
    float* s_lb = s_ls + 64;

    const int tid = threadIdx.x;
    for (int idx = tid; idx < 4096; idx += 256) {
        s_wq[idx] = Wq[idx];
        s_wk[idx] = Wk[idx];
        s_wv[idx] = Wv[idx];
        s_wg[idx] = Wg[idx];
    }
    s_wb[tid] = Wb[tid];
    if (tid < 64) { s_bg[tid] = bg[tid]; s_ls[tid] = ln_s[tid]; s_lb[tid] = ln_b[tid]; }
    __syncthreads();

    const int lane = tid & 31;
    const int wrp  = tid >> 5;
    const int jj   = tid & 63;
    const int pz   = tid >> 6;
    const int ph   = tid >> 2;
    const int hh   = tid & 3;

    for (int c = blockIdx.x; c < 1024; c += gridDim.x) {
        const int p0 = c * 64;

        for (int pp = wrp; pp < 64; pp += 8) {
            const float* xr = x + (p0 + pp) * DIM;
            float a = xr[lane];
            float b = xr[lane + 32];
            float sum = a + b;
            float sq = a * a + b * b;
            #pragma unroll
            for (int off = 16; off > 0; off >>= 1) {
                sum += __shfl_xor_sync(0xffffffffu, sum, off);
                sq  += __shfl_xor_sync(0xffffffffu, sq, off);
            }
            float mu  = sum * (1.0f / 64.0f);
            float var = sq * (1.0f / 64.0f) - mu * mu;
            float inv = rsqrtf(var + 1e-5f);
            s_xt[lane * 66 + pp]        = (a - mu) * inv * s_ls[lane]      + s_lb[lane];
            s_xt[(lane + 32) * 66 + pp] = (b - mu) * inv * s_ls[lane + 32] + s_lb[lane + 32];
        }
        __syncthreads();

        // bias + mask -> g_bm[k][h][q]
        {
            float acc = 0.0f;
            #pragma unroll 8
            for (int d = 0; d < 64; ++d)
                acc = fmaf(s_xt[d * 66 + ph], s_wb[d * 4 + hh], acc);
            const int flat = p0 + ph;
            const int r = flat >> 8;    // q
            const int cc = flat & 255;  // k
            g_bm[cc * (NH * NSEQ) + hh * NSEQ + r] = (mask[flat] != 0) ? acc : NEGINF;
        }

        u64 aq[8], ak[8], av[8], ag[8];
        #pragma unroll
        for (int m = 0; m < 8; ++m) { aq[m] = 0ull; ak[m] = 0ull; av[m] = 0ull; ag[m] = 0ull; }

        #pragma unroll 2
        for (int d = 0; d < 64; ++d) {
            const u64 wq2 = dup2(s_wq[d * 64 + jj]);
            const u64 wk2 = dup2(s_wk[d * 64 + jj]);
            const u64 wv2 = dup2(s_wv[d * 64 + jj]);
            const u64 wg2 = dup2(s_wg[d * 64 + jj]);
            const u64* xp = (const u64*)(s_xt + d * 66 + pz * 16);
            #pragma unroll
            for (int m = 0; m < 8; ++m) {
                const u64 xv = xp[m];
                fma2(aq[m], xv, wq2);
                fma2(ak[m], xv, wk2);
                fma2(av[m], xv, wv2);
                fma2(ag[m], xv, wg2);
            }
        }

        #pragma unroll
        for (int m = 0; m < 8; ++m) {
            const int o = (p0 + pz * 16 + 2 * m) * 64 + jj;
            float v0, v1;
            unpack2(aq[m], v0, v1); g_q[o] = v0; g_q[o + 64] = v1;
            unpack2(ak[m], v0, v1); g_k[o] = v0; g_k[o + 64] = v1;
            unpack2(av[m], v0, v1); g_v[o] = v0; g_v[o + 64] = v1;
            unpack2(ag[m], v0, v1);
            g_gate[o]      = 1.0f / (1.0f + __expf(-(v0 + s_bg[jj])));
            g_gate[o + 64] = 1.0f / (1.0f + __expf(-(v1 + s_bg[jj])));
        }
        __syncthreads();
    }
}

// ---------------------------------------------------------------------------
// Kernel 2: attention + gate + output projection, fused. Block = row i.
// 256 threads: thread = (q-group-of-4, head). K in SMEM as bf16 [kk][h][16],
// V fp32 head-interleaved [kk][j][h][4]. 2-stage software pipeline: K+bias
// for kk+1 prefetched while computing kk.
// ---------------------------------------------------------------------------
__global__ __launch_bounds__(256, 1) void attn_kernel(
    const float* __restrict__ Wo, const float* __restrict__ bo,
    float* __restrict__ out)
{
    extern __shared__ float sm[];
    unsigned int* s_kb = (unsigned int*)sm;   // 8192 u32 (256 kk x 32) bf16x2
    float* s_v = sm + 8192;                   // 16384 f, permuted [kk][j][h][4]
    // epilogue aliases (after attention, K/V dead):
    float* s_goT = sm;            // [64 d][260] = 16640 f
    float* s_wo  = sm + 16640;    // 4096
    float* s_bo  = sm + 20736;    // 64

    const int i   = blockIdx.x;
    const int tid = threadIdx.x;
    const int qg  = tid >> 2;     // 0..63
    const int h   = tid & 3;
    const int q0  = qg * 4;
    const int base = i * (NSEQ * DIM);

    // Stage K (fp32 -> bf16x2, layout [kk][h*8 + j*2 + t]) and V (permuted fp32)
    {
        const float4* gk4 = (const float4*)(g_k + base);
        const float4* gv4 = (const float4*)(g_v + base);
        #pragma unroll
        for (int it = 0; it < 16; ++it) {
            const int idx = it * 256 + tid;      // f4 index, 4096 total
            const int kk = idx >> 4;
            const int d4 = idx & 15;             // h = d4>>2, j = d4&3
            // V
            const int dstv = kk * 64 + (d4 & 3) * 16 + (d4 >> 2) * 4;
            float4 kv = gk4[idx];
            *(float4*)(s_v + dstv) = gv4[idx];
            // K -> bf16x2 pair
            unsigned int lo, hi2;
            {
                __nv_bfloat162 b0 = __floats2bfloat162_rn(kv.x, kv.y);
                __nv_bfloat162 b1 = __floats2bfloat162_rn(kv.z, kv.w);
                lo  = *(unsigned int*)&b0;
                hi2 = *(unsigned int*)&b1;
            }
            const int dstk = kk * 32 + (d4 >> 2) * 8 + (d4 & 3) * 2;
            s_kb[dstk]     = lo;
            s_kb[dstk + 1] = hi2;
        }
    }

    // q registers for 4 q's, pre-scaled by 1/sqrt(16)
    u64 qr[4][8];
    {
        const u64 sc = dup2(0.25f);
        #pragma unroll
        for (int qq = 0; qq < 4; ++qq) {
            const ulonglong2* q2 = (const ulonglong2*)(g_q + base + (q0 + qq) * 64 + h * 16);
            #pragma unroll
            for (int j = 0; j < 4; ++j) {
                ulonglong2 t = q2[j];
                qr[qq][2 * j]     = mul2(t.x, sc);
                qr[qq][2 * j + 1] = mul2(t.y, sc);
            }
        }
    }
    __syncthreads();

    u64 acc[4][8];
    #pragma unroll
    for (int qq = 0; qq < 4; ++qq)
        #pragma unroll
        for (int m = 0; m < 8; ++m) acc[qq][m] = 0ull;
    float l[4] = {0.f, 0.f, 0.f, 0.f};

    const float* bmb = g_bm + h * NSEQ + q0;           // + kk*1024
    const unsigned int* kbb = s_kb + h * 8;            // + kk*32

    // pipeline prologue: K + bias for kk=0
    uint4 kc0 = *(const uint4*)(kbb);
    uint4 kc1 = *(const uint4*)(kbb + 4);
    float4 bmc = *(const float4*)bmb;

    #pragma unroll 2
    for (int kk = 0; kk < 256; ++kk) {
        // prefetch kk+1
        uint4 kn0, kn1;
        float4 bmn;
        if (kk < 255) {
            kn0 = *(const uint4*)(kbb + (kk + 1) * 32);
            kn1 = *(const uint4*)(kbb + (kk + 1) * 32 + 4);
            bmn = __ldg((const float4*)(bmb + (kk + 1) * (NH * NSEQ)));
        }

        // convert K bf16 -> fp32 pairs
        u64 kb[8];
        kb[0] = bf2f2(kc0.x); kb[1] = bf2f2(kc0.y);
        kb[2] = bf2f2(kc0.z); kb[3] = bf2f2(kc0.w);
        kb[4] = bf2f2(kc1.x); kb[5] = bf2f2(kc1.y);
        kb[6] = bf2f2(kc1.z); kb[7] = bf2f2(kc1.w);

        // scores for 4 q's (independent chains, ILP 8)
        float p[4];
        #pragma unroll
        for (int qq = 0; qq < 4; ++qq) {
            u64 t0 = mul2(qr[qq][0], kb[0]);
            u64 t1 = mul2(qr[qq][1], kb[1]);
            fma2(t0, qr[qq][2], kb[2]);
            fma2(t1, qr[qq][3], kb[3]);
            fma2(t0, qr[qq][4], kb[4]);
            fma2(t1, qr[qq][5], kb[5]);
            fma2(t0, qr[qq][6], kb[6]);
            fma2(t1, qr[qq][7], kb[7]);
            const u64 ts = add2(t0, t1);
            float lo, hi;
            unpack2(ts, lo, hi);
            const float bmq = (qq == 0) ? bmc.x : (qq == 1) ? bmc.y
                              : (qq == 2) ? bmc.z : bmc.w;
            p[qq] = __expf(lo + hi + bmq);
            l[qq] += p[qq];
        }

        // V (fp32) + PV
        u64 vb[8];
        {
            const ulonglong2* vpu = (const ulonglong2*)(s_v + kk * 64);
            #pragma unroll
            for (int j = 0; j < 4; ++j) {
                ulonglong2 t = vpu[j * 4 + h];
                vb[2 * j]     = t.x;
                vb[2 * j + 1] = t.y;
            }
        }
        const u64 p0d = dup2(p[0]);
        const u64 p1d = dup2(p[1]);
        const u64 p2d = dup2(p[2]);
        const u64 p3d = dup2(p[3]);
        #pragma unroll
        for (int m = 0; m < 8; ++m) {
            fma2(acc[0][m], p0d, vb[m]);
            fma2(acc[1][m], p1d, vb[m]);
            fma2(acc[2][m], p2d, vb[m]);
            fma2(acc[3][m], p3d, vb[m]);
        }

        kc0 = kn0; kc1 = kn1; bmc = bmn;
    }

    __syncthreads();   // K/V reads done; smem re-used

    // gate * normalize -> s_goT[d][q] (stride 260)
    #pragma unroll
    for (int qq = 0; qq < 4; ++qq) {
        const float inv = 1.0f / l[qq];
        const u64 iv = dup2(inv);
        const ulonglong2* g2 = (const ulonglong2*)(g_gate + base + (q0 + qq) * 64 + h * 16);
        #pragma unroll
        for (int j = 0; j < 4; ++j) {
            ulonglong2 t = g2[j];
            u64 o0 = mul2(mul2(acc[qq][2 * j], iv), t.x);
            u64 o1 = mul2(mul2(acc[qq][2 * j + 1], iv), t.y);
            float a0, a1, b0, b1;
            unpack2(o0, a0, a1);
            unpack2(o1, b0, b1);
            const int db = h * 16 + j * 4;
            s_goT[(db + 0) * 260 + q0 + qq] = a0;
            s_goT[(db + 1) * 260 + q0 + qq] = a1;
            s_goT[(db + 2) * 260 + q0 + qq] = b0;
            s_goT[(db + 3) * 260 + q0 + qq] = b1;
        }
    }
    for (int idx = tid; idx < 4096; idx += 256) s_wo[idx] = Wo[idx];
    if (tid < 64) s_bo[tid] = bo[tid];
    __syncthreads();

    // out = go @ Wo + bo : thread = (col jj, 64-q group pz)
    const int jj = tid & 63;
    const int pz = tid >> 6;    // 0..3
    u64 oa[32];
    #pragma unroll
    for (int m = 0; m < 32; ++m) oa[m] = 0ull;
    #pragma unroll 2
    for (int d = 0; d < 64; ++d) {
        const u64 w2 = dup2(s_wo[d * 64 + jj]);
        const u64* gp = (const u64*)(s_goT + d * 260 + pz * 64);
        #pragma unroll
        for (int m = 0; m < 32; ++m) fma2(oa[m], gp[m], w2);
    }
    const float bov = s_bo[jj];
    float* op = out + (i * 256 + pz * 64) * 64 + jj;
    #pragma unroll
    for (int m = 0; m < 32; ++m) {
        float lo, hi;
        unpack2(oa[m], lo, hi);
        op[(2 * m) * 64]     = lo + bov;
        op[(2 * m + 1) * 64] = hi + bov;
    }
}

// ---------------------------------------------------------------------------
extern "C" void kernel_launch(void* const* d_in, const int* in_sizes, int n_in,
                              void* d_out, int out_size)
{
    const float* x    = (const float*)d_in[0];
    const int*   mask = (const int*)d_in[1];
    const float* ln_s = (const float*)d_in[2];
    const float* ln_b = (const float*)d_in[3];
    const float* Wq   = (const float*)d_in[4];
    const float* Wk   = (const float*)d_in[5];
    const float* Wv   = (const float*)d_in[6];
    const float* Wg   = (const float*)d_in[7];
    const float* bg   = (const float*)d_in[8];
    const float* Wb   = (const float*)d_in[9];
    const float* Wo   = (const float*)d_in[10];
    const float* bo   = (const float*)d_in[11];
    float* out = (float*)d_out;
    (void)in_sizes; (void)n_in; (void)out_size;

    const int sm1 = (4 * 4096 + 256 + 64 * 66 + 3 * 64) * (int)sizeof(float);
    const int sm2 = (8192 + 16384) * (int)sizeof(float);   // 98304 B
    cudaFuncSetAttribute(proj_kernel, cudaFuncAttributeMaxDynamicSharedMemorySize, sm1);
    cudaFuncSetAttribute(attn_kernel, cudaFuncAttributeMaxDynamicSharedMemorySize, sm2);

    proj_kernel<<<296, 256, sm1>>>(x, mask, ln_s, ln_b, Wq, Wk, Wv, Wg, bg, Wb);
    attn_kernel<<<256, 256, sm2>>>(Wo, bo, out);
}

// round 10
// speedup vs baseline: 3.2452x; 1.1988x over previous
#include <cuda_runtime.h>
#include <cuda_fp16.h>
#include <math.h>
#include <string.h>

#define NSEQ 256
#define DIM 64
#define NH 4
#define NPOS (NSEQ * NSEQ)
#define NEGINF -1000000000.0f

typedef unsigned long long u64;
typedef unsigned int u32;

// ---- packed fp32x2 helpers (proj + epilogue) ----
__device__ __forceinline__ u64 pack2(float lo, float hi) {
    u64 r; asm("mov.b64 %0, {%1, %2};" : "=l"(r) : "f"(lo), "f"(hi)); return r;
}
__device__ __forceinline__ u64 dup2(float v) { return pack2(v, v); }
__device__ __forceinline__ void unpack2(u64 v, float& lo, float& hi) {
    asm("mov.b64 {%0, %1}, %2;" : "=f"(lo), "=f"(hi) : "l"(v));
}
__device__ __forceinline__ void fma2(u64& d, u64 a, u64 b) {
    asm("fma.rn.f32x2 %0, %1, %2, %0;" : "+l"(d) : "l"(a), "l"(b));
}
__device__ __forceinline__ u64 mul2(u64 a, u64 b) {
    u64 r; asm("mul.rn.f32x2 %0, %1, %2;" : "=l"(r) : "l"(a), "l"(b)); return r;
}

// pack two floats as fp16x2 (low half = a)
__device__ __forceinline__ u32 hpack(float a, float b) {
    __half2 p = __floats2half2_rn(a, b);
    u32 r; memcpy(&r, &p, 4); return r;
}

// mma.sync m16n8k16 row.col f32.f16.f16.f32, D = A*B + D
__device__ __forceinline__ void mma16816(float* c, const u32* a, const u32* b) {
    asm volatile(
        "mma.sync.aligned.m16n8k16.row.col.f32.f16.f16.f32 "
        "{%0,%1,%2,%3}, {%4,%5,%6,%7}, {%8,%9}, {%0,%1,%2,%3};"
        : "+f"(c[0]), "+f"(c[1]), "+f"(c[2]), "+f"(c[3])
        : "r"(a[0]), "r"(a[1]), "r"(a[2]), "r"(a[3]), "r"(b[0]), "r"(b[1]));
}

// Scratch
__device__ float g_q[NPOS * DIM];
__device__ float g_k[NPOS * DIM];
__device__ float g_v[NPOS * DIM];
__device__ float g_gate[NPOS * DIM];
__device__ float g_bm[NH * NSEQ * NSEQ];   // [h][q][k]

// ---------------------------------------------------------------------------
// Kernel 1 (persistent): LayerNorm + Q/K/V/Gate projections + fused bias/mask.
// ---------------------------------------------------------------------------
__global__ __launch_bounds__(256, 2) void proj_kernel(
    const float* __restrict__ x, const int* __restrict__ mask,
    const float* __restrict__ ln_s, const float* __restrict__ ln_b,
    const float* __restrict__ Wq, const float* __restrict__ Wk,
    const float* __restrict__ Wv, const float* __restrict__ Wg,
    const float* __restrict__ bg, const float* __restrict__ Wb)
{
    extern __shared__ float sm[];
    float* s_wq = sm;                 // 4096
    float* s_wk = s_wq + 4096;
    float* s_wv = s_wk + 4096;
    float* s_wg = s_wv + 4096;
    float* s_wb = s_wg + 4096;        // 256
    float* s_xt = s_wb + 256;         // [d][pos] stride 66
    float* s_bg = s_xt + 64 * 66;
    float* s_ls = s_bg + 64;
    float* s_lb = s_ls + 64;

    const int tid = threadIdx.x;
    for (int idx = tid; idx < 4096; idx += 256) {
        s_wq[idx] = Wq[idx];
        s_wk[idx] = Wk[idx];
        s_wv[idx] = Wv[idx];
        s_wg[idx] = Wg[idx];
    }
    s_wb[tid] = Wb[tid];
    if (tid < 64) { s_bg[tid] = bg[tid]; s_ls[tid] = ln_s[tid]; s_lb[tid] = ln_b[tid]; }
    __syncthreads();

    const int lane = tid & 31;
    const int wrp  = tid >> 5;
    const int jj   = tid & 63;
    const int pz   = tid >> 6;
    const int ph   = tid >> 2;
    const int hh   = tid & 3;

    for (int c = blockIdx.x; c < 1024; c += gridDim.x) {
        const int p0 = c * 64;

        for (int pp = wrp; pp < 64; pp += 8) {
            const float* xr = x + (p0 + pp) * DIM;
            float a = xr[lane];
            float b = xr[lane + 32];
            float sum = a + b;
            float sq = a * a + b * b;
            #pragma unroll
            for (int off = 16; off > 0; off >>= 1) {
                sum += __shfl_xor_sync(0xffffffffu, sum, off);
                sq  += __shfl_xor_sync(0xffffffffu, sq, off);
            }
            float mu  = sum * (1.0f / 64.0f);
            float var = sq * (1.0f / 64.0f) - mu * mu;
            float inv = rsqrtf(var + 1e-5f);
            s_xt[lane * 66 + pp]        = (a - mu) * inv * s_ls[lane]      + s_lb[lane];
            s_xt[(lane + 32) * 66 + pp] = (b - mu) * inv * s_ls[lane + 32] + s_lb[lane + 32];
        }
        __syncthreads();

        // bias + mask -> g_bm[h][q][k]
        {
            float acc = 0.0f;
            #pragma unroll 8
            for (int d = 0; d < 64; ++d)
                acc = fmaf(s_xt[d * 66 + ph], s_wb[d * 4 + hh], acc);
            const int flat = p0 + ph;
            const int r = flat >> 8;    // q
            const int cc = flat & 255;  // k
            g_bm[hh * 65536 + r * 256 + cc] = (mask[flat] != 0) ? acc : NEGINF;
        }

        u64 aq[8], ak[8], av[8], ag[8];
        #pragma unroll
        for (int m = 0; m < 8; ++m) { aq[m] = 0ull; ak[m] = 0ull; av[m] = 0ull; ag[m] = 0ull; }

        #pragma unroll 2
        for (int d = 0; d < 64; ++d) {
            const u64 wq2 = dup2(s_wq[d * 64 + jj]);
            const u64 wk2 = dup2(s_wk[d * 64 + jj]);
            const u64 wv2 = dup2(s_wv[d * 64 + jj]);
            const u64 wg2 = dup2(s_wg[d * 64 + jj]);
            const u64* xp = (const u64*)(s_xt + d * 66 + pz * 16);
            #pragma unroll
            for (int m = 0; m < 8; ++m) {
                const u64 xv = xp[m];
                fma2(aq[m], xv, wq2);
                fma2(ak[m], xv, wk2);
                fma2(av[m], xv, wv2);
                fma2(ag[m], xv, wg2);
            }
        }

        #pragma unroll
        for (int m = 0; m < 8; ++m) {
            const int o = (p0 + pz * 16 + 2 * m) * 64 + jj;
            float v0, v1;
            unpack2(aq[m], v0, v1); g_q[o] = v0; g_q[o + 64] = v1;
            unpack2(ak[m], v0, v1); g_k[o] = v0; g_k[o + 64] = v1;
            unpack2(av[m], v0, v1); g_v[o] = v0; g_v[o + 64] = v1;
            unpack2(ag[m], v0, v1);
            g_gate[o]      = 1.0f / (1.0f + __expf(-(v0 + s_bg[jj])));
            g_gate[o + 64] = 1.0f / (1.0f + __expf(-(v1 + s_bg[jj])));
        }
        __syncthreads();
    }
}

// ---------------------------------------------------------------------------
// Attention unit: warp computes O[64 q][16 d], row-sums, for (i, h, q0).
// ---------------------------------------------------------------------------
__device__ __forceinline__ void run_unit(
    int i, int h, int q0, int g, int t,
    const u32* __restrict__ s_kw, const u32* __restrict__ s_vw,
    float oc[4][2][4], float ls[4][2])
{
    // Q frags (pre-scaled by 1/sqrt(16))
    u32 qa[4][4];
    {
        const float2* qp = (const float2*)g_q;
        #pragma unroll
        for (int mt = 0; mt < 4; ++mt) {
            const int r0 = i * 256 + q0 + mt * 16 + g;
            float2 f0 = qp[r0 * 32 + h * 8 + t];
            float2 f1 = qp[(r0 + 8) * 32 + h * 8 + t];
            float2 f2 = qp[r0 * 32 + h * 8 + 4 + t];
            float2 f3 = qp[(r0 + 8) * 32 + h * 8 + 4 + t];
            qa[mt][0] = hpack(f0.x * 0.25f, f0.y * 0.25f);
            qa[mt][1] = hpack(f1.x * 0.25f, f1.y * 0.25f);
            qa[mt][2] = hpack(f2.x * 0.25f, f2.y * 0.25f);
            qa[mt][3] = hpack(f3.x * 0.25f, f3.y * 0.25f);
        }
    }
    #pragma unroll
    for (int mt = 0; mt < 4; ++mt) {
        ls[mt][0] = 0.f; ls[mt][1] = 0.f;
        #pragma unroll
        for (int nd = 0; nd < 2; ++nd)
            #pragma unroll
            for (int r = 0; r < 4; ++r) oc[mt][nd][r] = 0.f;
    }

    const float2* bp = (const float2*)g_bm + h * 32768 + (q0 + g) * 128 + t;
    const u32* kp = s_kw + h * 2048 + g * 8 + t;
    const u32* vp = s_vw + (h * 16 + g) * 132 + t;

    float2 bA[16], bB[16];   // [mt][nt][rr] -> mt*4 + nt*2 + rr
    #pragma unroll
    for (int mt = 0; mt < 4; ++mt)
        #pragma unroll
        for (int nt = 0; nt < 2; ++nt)
            #pragma unroll
            for (int rr = 0; rr < 2; ++rr)
                bA[mt * 4 + nt * 2 + rr] = __ldg(bp + mt * 2048 + rr * 1024 + nt * 4);

    auto body = [&](int c, const float2* bu, float2* bpf, int cn) {
        // K frags
        u32 kb[2][2];
        #pragma unroll
        for (int nt = 0; nt < 2; ++nt) {
            kb[nt][0] = kp[(c * 16 + nt * 8) * 8];
            kb[nt][1] = kp[(c * 16 + nt * 8) * 8 + 4];
        }
        // S frags init = bias, then QK MMA
        float sc[4][2][4];
        #pragma unroll
        for (int mt = 0; mt < 4; ++mt)
            #pragma unroll
            for (int nt = 0; nt < 2; ++nt) {
                sc[mt][nt][0] = bu[mt * 4 + nt * 2 + 0].x;
                sc[mt][nt][1] = bu[mt * 4 + nt * 2 + 0].y;
                sc[mt][nt][2] = bu[mt * 4 + nt * 2 + 1].x;
                sc[mt][nt][3] = bu[mt * 4 + nt * 2 + 1].y;
            }
        #pragma unroll
        for (int mt = 0; mt < 4; ++mt)
            #pragma unroll
            for (int nt = 0; nt < 2; ++nt)
                mma16816(sc[mt][nt], qa[mt], kb[nt]);
        // prefetch bias for chunk cn
        if (cn < 16) {
            #pragma unroll
            for (int mt = 0; mt < 4; ++mt)
                #pragma unroll
                for (int nt = 0; nt < 2; ++nt)
                    #pragma unroll
                    for (int rr = 0; rr < 2; ++rr)
                        bpf[mt * 4 + nt * 2 + rr] =
                            __ldg(bp + mt * 2048 + rr * 1024 + cn * 8 + nt * 4);
        }
        // exp + row sums + P frags
        u32 pa[4][4];
        #pragma unroll
        for (int mt = 0; mt < 4; ++mt) {
            float e00 = __expf(sc[mt][0][0]);
            float e01 = __expf(sc[mt][0][1]);
            float e02 = __expf(sc[mt][0][2]);
            float e03 = __expf(sc[mt][0][3]);
            float e10 = __expf(sc[mt][1][0]);
            float e11 = __expf(sc[mt][1][1]);
            float e12 = __expf(sc[mt][1][2]);
            float e13 = __expf(sc[mt][1][3]);
            ls[mt][0] += (e00 + e01) + (e10 + e11);
            ls[mt][1] += (e02 + e03) + (e12 + e13);
            pa[mt][0] = hpack(e00, e01);
            pa[mt][1] = hpack(e02, e03);
            pa[mt][2] = hpack(e10, e11);
            pa[mt][3] = hpack(e12, e13);
        }
        // V frags (hi part 0, lo part 1)
        u32 vb[2][2][2];
        #pragma unroll
        for (int part = 0; part < 2; ++part)
            #pragma unroll
            for (int nd = 0; nd < 2; ++nd) {
                const u32* vq = vp + (part * 64 + nd * 8) * 132 + c * 8;
                vb[part][nd][0] = vq[0];
                vb[part][nd][1] = vq[4];
            }
        // PV MMAs
        #pragma unroll
        for (int mt = 0; mt < 4; ++mt)
            #pragma unroll
            for (int nd = 0; nd < 2; ++nd) {
                mma16816(oc[mt][nd], pa[mt], vb[0][nd]);
                mma16816(oc[mt][nd], pa[mt], vb[1][nd]);
            }
    };

    #pragma unroll 1
    for (int cc = 0; cc < 8; ++cc) {
        body(2 * cc,     bA, bB, 2 * cc + 1);
        body(2 * cc + 1, bB, bA, 2 * cc + 2);
    }
}

// ---------------------------------------------------------------------------
// Kernel 2: MMA attention + gate + output projection, fused. Block = row i.
// 256 threads = 8 warps; warp = (h = w&3, q-quarter pair). Two 64-q units.
// ---------------------------------------------------------------------------
__global__ __launch_bounds__(256, 1) void attn_kernel(
    const float* __restrict__ Wo, const float* __restrict__ bo,
    float* __restrict__ out)
{
    extern __shared__ float smf[];
    u32* s_kw = (u32*)smf;                              // 8192 u32 = 32 KB
    __half* s_vt = (__half*)(smf + 8192);               // 128 rows x 264 fp16
    const u32* s_vw = (const u32*)(smf + 8192);
    // epilogue aliases (after sync):
    float* s_goT = smf;             // [64][260]
    float* s_wo  = smf + 16640;     // 4096
    float* s_bo  = smf + 20736;     // 64

    const int i = blockIdx.x;
    const int tid = threadIdx.x;
    const int w = tid >> 5, lane = tid & 31;
    const int h = w & 3, qhi = w >> 2;
    const int g = lane >> 2, t = lane & 3;

    // ---- stage K (fp16 pairs) and V^T (fp16 hi/lo, transposed) ----
    {
        const float4* gk4 = (const float4*)(g_k + i * 16384);
        const float4* gv4 = (const float4*)(g_v + i * 16384);
        #pragma unroll
        for (int it = 0; it < 16; ++it) {
            const int idx = it * 256 + tid;
            const int key = idx >> 4, f4 = idx & 15;
            const int hh = f4 >> 2, quad = f4 & 3;
            float4 kv = gk4[idx];
            const int ka = (hh * 256 + key) * 8 + quad * 2;
            s_kw[ka]     = hpack(kv.x, kv.y);
            s_kw[ka + 1] = hpack(kv.z, kv.w);
            float4 vv = gv4[idx];
            float ve[4] = {vv.x, vv.y, vv.z, vv.w};
            #pragma unroll
            for (int e = 0; e < 4; ++e) {
                __half hi = __float2half_rn(ve[e]);
                __half lo = __float2half_rn(ve[e] - __half2float(hi));
                const int dl = hh * 16 + quad * 4 + e;
                s_vt[dl * 264 + key]          = hi;
                s_vt[(64 + dl) * 264 + key]   = lo;
            }
        }
    }
    __syncthreads();

    float oc[2][4][2][4];
    float inv[2][4][2];
    #pragma unroll 1
    for (int u = 0; u < 2; ++u) {
        const int q0 = qhi * 128 + u * 64;
        float ls[4][2];
        run_unit(i, h, q0, g, t, s_kw, s_vw, oc[u], ls);
        #pragma unroll
        for (int mt = 0; mt < 4; ++mt)
            #pragma unroll
            for (int rr = 0; rr < 2; ++rr) {
                float v = ls[mt][rr];
                v += __shfl_xor_sync(0xffffffffu, v, 1);
                v += __shfl_xor_sync(0xffffffffu, v, 2);
                inv[u][mt][rr] = 1.0f / v;
            }
    }

    // normalize + gate (registers only)
    {
        const float2* gp = (const float2*)g_gate;
        #pragma unroll
        for (int u = 0; u < 2; ++u) {
            const int q0 = qhi * 128 + u * 64;
            #pragma unroll
            for (int mt = 0; mt < 4; ++mt) {
                const int qr = i * 256 + q0 + mt * 16 + g;
                #pragma unroll
                for (int nd = 0; nd < 2; ++nd) {
                    float2 g0 = gp[qr * 32 + h * 8 + nd * 4 + t];
                    float2 g1 = gp[(qr + 8) * 32 + h * 8 + nd * 4 + t];
                    oc[u][mt][nd][0] *= inv[u][mt][0] * g0.x;
                    oc[u][mt][nd][1] *= inv[u][mt][0] * g0.y;
                    oc[u][mt][nd][2] *= inv[u][mt][1] * g1.x;
                    oc[u][mt][nd][3] *= inv[u][mt][1] * g1.y;
                }
            }
        }
    }

    __syncthreads();   // all K/V smem reads done; re-use as goT

    // write goT [d][q] stride 260
    #pragma unroll
    for (int u = 0; u < 2; ++u) {
        const int q0 = qhi * 128 + u * 64;
        #pragma unroll
        for (int mt = 0; mt < 4; ++mt) {
            const int qr = q0 + mt * 16 + g;
            #pragma unroll
            for (int nd = 0; nd < 2; ++nd) {
                const int d0 = h * 16 + nd * 8 + 2 * t;
                s_goT[d0 * 260 + qr]           = oc[u][mt][nd][0];
                s_goT[(d0 + 1) * 260 + qr]     = oc[u][mt][nd][1];
                s_goT[d0 * 260 + qr + 8]       = oc[u][mt][nd][2];
                s_goT[(d0 + 1) * 260 + qr + 8] = oc[u][mt][nd][3];
            }
        }
    }
    for (int idx = tid; idx < 4096; idx += 256) s_wo[idx] = Wo[idx];
    if (tid < 64) s_bo[tid] = bo[tid];
    __syncthreads();

    // out = go @ Wo + bo
    const int jj = tid & 63;
    const int pz = tid >> 6;    // 0..3
    u64 oa[32];
    #pragma unroll
    for (int m = 0; m < 32; ++m) oa[m] = 0ull;
    #pragma unroll 2
    for (int d = 0; d < 64; ++d) {
        const u64 w2 = dup2(s_wo[d * 64 + jj]);
        const u64* gpt = (const u64*)(s_goT + d * 260 + pz * 64);
        #pragma unroll
        for (int m = 0; m < 32; ++m) fma2(oa[m], gpt[m], w2);
    }
    const float bov = s_bo[jj];
    float* op = out + (i * 256 + pz * 64) * 64 + jj;
    #pragma unroll
    for (int m = 0; m < 32; ++m) {
        float lo, hi;
        unpack2(oa[m], lo, hi);
        op[(2 * m) * 64]     = lo + bov;
        op[(2 * m + 1) * 64] = hi + bov;
    }
}

// ---------------------------------------------------------------------------
extern "C" void kernel_launch(void* const* d_in, const int* in_sizes, int n_in,
                              void* d_out, int out_size)
{
    const float* x    = (const float*)d_in[0];
    const int*   mask = (const int*)d_in[1];
    const float* ln_s = (const float*)d_in[2];
    const float* ln_b = (const float*)d_in[3];
    const float* Wq   = (const float*)d_in[4];
    const float* Wk   = (const float*)d_in[5];
    const float* Wv   = (const float*)d_in[6];
    const float* Wg   = (const float*)d_in[7];
    const float* bg   = (const float*)d_in[8];
    const float* Wb   = (const float*)d_in[9];
    const float* Wo   = (const float*)d_in[10];
    const float* bo   = (const float*)d_in[11];
    float* out = (float*)d_out;
    (void)in_sizes; (void)n_in; (void)out_size;

    const int sm1 = (4 * 4096 + 256 + 64 * 66 + 3 * 64) * (int)sizeof(float);
    const int sm2 = 100352;   // 32 KB K + 66 KB V^T (epilogue aliases within)
    cudaFuncSetAttribute(proj_kernel, cudaFuncAttributeMaxDynamicSharedMemorySize, sm1);
    cudaFuncSetAttribute(attn_kernel, cudaFuncAttributeMaxDynamicSharedMemorySize, sm2);

    proj_kernel<<<296, 256, sm1>>>(x, mask, ln_s, ln_b, Wq, Wk, Wv, Wg, bg, Wb);
    attn_kernel<<<256, 256, sm2>>>(Wo, bo, out);
}